// round 17
// baseline (speedup 1.0000x reference)
#include <cuda_runtime.h>
#include <cfloat>
#include <cstdint>

#define CH          151
#define N_EDGES     47
#define GROUP_ROWS  32                    // rows per group == lanes
#define GROUP_F     (GROUP_ROWS * CH)     // 4832 floats per array
#define GROUP_V4    (GROUP_F / 4)         // 1208 float4
#define BUF_F       (2 * GROUP_F)         // p then t
#define RING        5                     // prefetch distance = RING-1 groups
#define NWARP       32
#define THREADS     (NWARP * 32)          // 1024
#define NEDGE_WARPS 16
#define SMEM_BYTES  (RING * BUF_F * 4)    // 193,280 B dynamic

// ---- topology-shared edge slots (validated in R14/R16) --------------------
//   type 0 PATH : edges (J0,J1) (J1,J2) (J2,J3)
//   type 1 STAR : edges (J0,J1) (J0,J2) (J0,J3)
//   type 2 PATH2: edges (J0,J1) (J1,J2)
// Edge direction is irrelevant (d*d sign-invariant). Mask channels use the
// ORIGINAL edge index (c*47+e post-transpose layout).
__constant__ int4 c_jnt[NEDGE_WARPS] = {
    {  0,  3,  6,  9}, { 27, 30, 33, 36}, { 39, 42, 45, 48}, { 51, 54, 57, 60},
    { 63, 66, 69, 72}, { 75, 78, 81, 84}, { 90, 93, 96, 99}, {102,105,108,111},
    {114,117,120,123}, {126,129,132,135}, {138,141,144,147}, { 24, 27, 39, 51},
    { 24, 63, 75, 18}, { 87, 90,102,114}, { 87,126,138,  9}, {  3, 15, 18, 18}};
__constant__ int4 c_me[NEDGE_WARPS] = {
    { 0, 1, 2,0}, {12,13,14,0}, {15,16,17,0}, {18,19,20,0},
    {21,22,23,0}, {24,25,26,0}, {32,33,34,0}, {35,36,37,0},
    {38,39,40,0}, {41,42,43,0}, {44,45,46,0}, { 7, 8, 9,0},
    {10,11, 6,0}, {27,28,29,0}, {30,31, 3,0}, { 4, 5, 0,0}};
__constant__ int c_type[NEDGE_WARPS] = {0,0,0,0,0,0,0,0,0,0,0,1,1,1,1,2};

// original edge tables (tail fallback only)
__constant__ int c_par3[N_EDGES] = {
    0,3,6,9,3,15,18,24,24,24,24,24,27,30,33,39,42,45,51,54,57,63,66,69,
    75,78,81,87,87,87,87,87,90,93,96,102,105,108,114,117,120,126,129,132,138,141,144};
__constant__ int c_chi3[N_EDGES] = {
    3,6,9,87,15,18,24,27,39,51,63,75,30,33,36,42,45,48,54,57,60,66,69,72,
    78,81,84,90,102,114,126,138,93,96,99,105,108,111,117,120,123,129,132,135,141,144,147};

// persistent accumulators; statically zero, last block resets after use
__device__ double   g_acc[2] = {0.0, 0.0};
__device__ unsigned g_ticket = 0;

extern __shared__ float smem_dyn[];

__device__ __forceinline__ void cp16(void* s, const void* g) {
    uint32_t sa = (uint32_t)__cvta_generic_to_shared(s);
    asm volatile("cp.async.cg.shared.global [%0], [%1], 16;" :: "r"(sa), "l"(g));
}

// one edge from q (masked pred) and t (raw target) joint coordinates
__device__ __forceinline__ void edge_contrib(
    float qpx, float qpy, float qpz, float qcx, float qcy, float qcz,
    float tpx, float tpy, float tpz, float tcx, float tcy, float tcz,
    const float* __restrict__ trow, int me, float& vel_acc)
{
    float dp0 = qpx - qcx, dp1 = qpy - qcy, dp2 = qpz - qcz;
    float dt0 = tpx - tcx, dt1 = tpy - tcy, dt2 = tpz - tcz;

    float np = fmaf(dp0, dp0, fmaf(dp1, dp1, dp2 * dp2));
    float nt = fmaf(dt0, dt0, fmaf(dt1, dt1, dt2 * dt2));

    // n==0 -> dp==0 -> d==0 regardless of clamp; exact vs ref
    float ip = rsqrtf(fmaxf(np, FLT_MIN));
    float it = rsqrtf(fmaxf(nt, FLT_MIN));

    float d0 = dp0 * ip - dt0 * it;
    float d1 = dp1 * ip - dt1 * it;
    float d2 = dp2 * ip - dt2 * it;

    if (trow[me]      != 0.f) vel_acc = fmaf(d0, d0, vel_acc);
    if (trow[47 + me] != 0.f) vel_acc = fmaf(d1, d1, vel_acc);
    if (trow[94 + me] != 0.f) vel_acc = fmaf(d2, d2, vel_acc);
}

// tail fallback straight from gmem (unused for this shape, kept for generality)
__device__ __forceinline__ void process_row_gmem(const float* __restrict__ p,
                                                 const float* __restrict__ t,
                                                 float& l1_acc, float& vel_acc)
{
    float l1 = 0.f;
    float q[CH];
    #pragma unroll 8
    for (int i = 0; i < CH; i++) {
        float tv = t[i];
        float pv = p[i];
        q[i] = (tv != 0.f) ? pv : 0.f;
        l1 += (tv != 0.f) ? fabsf(pv - tv) : 0.f;
    }
    l1_acc += l1;
    for (int e = 0; e < N_EDGES; e++) {
        int a = c_par3[e], b = c_chi3[e];
        edge_contrib(q[a], q[a+1], q[a+2], q[b], q[b+1], q[b+2],
                     t[a], t[a+1], t[a+2], t[b], t[b+1], t[b+2],
                     t, e, vel_acc);
    }
}

__global__ void __launch_bounds__(THREADS, 1)
reg_loss_kernel(const float* __restrict__ preds,
                const float* __restrict__ targets,
                float* __restrict__ out,
                int groups, int rows)
{
    __shared__ float s_red[2][NWARP];
    __shared__ bool  s_last;

    const int lane = threadIdx.x & 31;
    const int wloc = threadIdx.x >> 5;
    const int tid  = threadIdx.x;

    const int kcnt = (blockIdx.x < (unsigned)groups)
                   ? ((groups - 1 - blockIdx.x) / gridDim.x + 1) : 0;

    float l1_acc = 0.f, vel_acc = 0.f;

    // stage raw p and t of group-index j into ring buffer b (all threads)
    auto stage = [&](long j, int b) {
        const float4* gp = (const float4*)(preds   + (size_t)j * GROUP_F);
        const float4* gt = (const float4*)(targets + (size_t)j * GROUP_F);
        float4* dP = (float4*)(smem_dyn + (size_t)b * BUF_F);
        float4* dT = dP + GROUP_V4;
        #pragma unroll
        for (int i = 0; i < 2; i++) {
            int idx = tid + i * THREADS;
            if (idx < GROUP_V4) {
                cp16(dP + idx, gp + idx);
                cp16(dT + idx, gt + idx);
            }
        }
    };

    // ---- prologue: fill RING-1 slots (commit once per slot) ----
    #pragma unroll
    for (int j = 0; j < RING - 1; j++) {
        if (j < kcnt) stage(blockIdx.x + (long)j * gridDim.x, j);
        asm volatile("cp.async.commit_group;");
    }

    for (int k = 0; k < kcnt; k++) {
        // commits so far = (RING-1) + k; wait_group RING-2 => groups 0..k done
        asm volatile("cp.async.wait_group %0;" :: "n"(RING - 2) : "memory");
        // all warps past this barrier => everyone finished reading group k-1,
        // so staging into buffer (k-1)%RING below is race-free; barrier also
        // publishes every thread's cp.async writes for group k.
        __syncthreads();

        {   // issue group k+RING-1 (distance = RING-1 iterations)
            int j = k + RING - 1;
            if (j < kcnt)
                stage(blockIdx.x + (long)j * gridDim.x, j % RING);
            asm volatile("cp.async.commit_group;");   // empty commit in drain
        }

        const float* sP = smem_dyn + (size_t)(k % RING) * BUF_F;
        const float* sT = sP + GROUP_F;
        const float* prow = sP + lane * CH;   // stride 151 words: conflict-free
        const float* trow = sT + lane * CH;

        if (wloc < NEDGE_WARPS) {
            // ---- edge warps: slot wloc, lane = row ----
            const int4 J  = c_jnt[wloc];
            const int4 ME = c_me[wloc];
            const int  ty = c_type[wloc];

            float t0x = trow[J.x], t0y = trow[J.x+1], t0z = trow[J.x+2];
            float t1x = trow[J.y], t1y = trow[J.y+1], t1z = trow[J.y+2];
            float t2x = trow[J.z], t2y = trow[J.z+1], t2z = trow[J.z+2];
            float t3x = trow[J.w], t3y = trow[J.w+1], t3z = trow[J.w+2];
            float p0x = prow[J.x], p0y = prow[J.x+1], p0z = prow[J.x+2];
            float p1x = prow[J.y], p1y = prow[J.y+1], p1z = prow[J.y+2];
            float p2x = prow[J.z], p2y = prow[J.z+1], p2z = prow[J.z+2];
            float p3x = prow[J.w], p3y = prow[J.w+1], p3z = prow[J.w+2];

            // mask preds on the fly (q = (t!=0) ? p : 0)
            float q0x = (t0x != 0.f) ? p0x : 0.f, q0y = (t0y != 0.f) ? p0y : 0.f,
                  q0z = (t0z != 0.f) ? p0z : 0.f;
            float q1x = (t1x != 0.f) ? p1x : 0.f, q1y = (t1y != 0.f) ? p1y : 0.f,
                  q1z = (t1z != 0.f) ? p1z : 0.f;
            float q2x = (t2x != 0.f) ? p2x : 0.f, q2y = (t2y != 0.f) ? p2y : 0.f,
                  q2z = (t2z != 0.f) ? p2z : 0.f;
            float q3x = (t3x != 0.f) ? p3x : 0.f, q3y = (t3y != 0.f) ? p3y : 0.f,
                  q3z = (t3z != 0.f) ? p3z : 0.f;

            if (ty == 0) {            // PATH
                edge_contrib(q0x,q0y,q0z, q1x,q1y,q1z,
                             t0x,t0y,t0z, t1x,t1y,t1z, trow, ME.x, vel_acc);
                edge_contrib(q1x,q1y,q1z, q2x,q2y,q2z,
                             t1x,t1y,t1z, t2x,t2y,t2z, trow, ME.y, vel_acc);
                edge_contrib(q2x,q2y,q2z, q3x,q3y,q3z,
                             t2x,t2y,t2z, t3x,t3y,t3z, trow, ME.z, vel_acc);
            } else if (ty == 1) {     // STAR
                edge_contrib(q0x,q0y,q0z, q1x,q1y,q1z,
                             t0x,t0y,t0z, t1x,t1y,t1z, trow, ME.x, vel_acc);
                edge_contrib(q0x,q0y,q0z, q2x,q2y,q2z,
                             t0x,t0y,t0z, t2x,t2y,t2z, trow, ME.y, vel_acc);
                edge_contrib(q0x,q0y,q0z, q3x,q3y,q3z,
                             t0x,t0y,t0z, t3x,t3y,t3z, trow, ME.z, vel_acc);
            } else {                  // PATH2
                edge_contrib(q0x,q0y,q0z, q1x,q1y,q1z,
                             t0x,t0y,t0z, t1x,t1y,t1z, trow, ME.x, vel_acc);
                edge_contrib(q1x,q1y,q1z, q2x,q2y,q2z,
                             t1x,t1y,t1z, t2x,t2y,t2z, trow, ME.y, vel_acc);
            }
        } else {
            // ---- L1 warps: channels w2, w2+16, ... ; lane = row ----
            int w2 = wloc - NEDGE_WARPS;
            #pragma unroll 5
            for (int c = w2; c < CH; c += 16) {
                float tv = trow[c];
                float pv = prow[c];
                l1_acc += (tv != 0.f) ? fabsf(pv - tv) : 0.f;
            }
        }
        // NO trailing sync: next iteration's barrier gates buffer reuse.
    }

    // tail rows (rows % 32) straight from gmem (empty for this dataset)
    if (blockIdx.x == 0 && wloc == 0) {
        for (int row = groups * GROUP_ROWS + lane; row < rows; row += 32) {
            process_row_gmem(preds + (size_t)row * CH,
                             targets + (size_t)row * CH, l1_acc, vel_acc);
        }
    }

    // ---- warp reduce ----
    #pragma unroll
    for (int o = 16; o > 0; o >>= 1) {
        l1_acc  += __shfl_down_sync(0xFFFFFFFFu, l1_acc,  o);
        vel_acc += __shfl_down_sync(0xFFFFFFFFu, vel_acc, o);
    }
    if (lane == 0) { s_red[0][wloc] = l1_acc; s_red[1][wloc] = vel_acc; }
    __syncthreads();

    // ---- block reduce + global accumulate + last-block finalize ----
    if (threadIdx.x == 0) {
        float a = 0.f, v = 0.f;
        #pragma unroll
        for (int i = 0; i < NWARP; i++) { a += s_red[0][i]; v += s_red[1][i]; }
        atomicAdd(&g_acc[0], (double)a);
        atomicAdd(&g_acc[1], (double)v);
        __threadfence();
        unsigned tk = atomicAdd(&g_ticket, 1u);
        s_last = (tk == gridDim.x - 1);
    }
    __syncthreads();

    if (s_last && threadIdx.x == 0) {
        double l1  = g_acc[0] / ((double)rows * (double)CH);
        double vel = g_acc[1] / ((double)rows * (double)(N_EDGES * 3));
        out[0] = (float)(l1 + 0.1 * vel);
        // reset persistent state so every graph replay starts identically
        g_acc[0] = 0.0;
        g_acc[1] = 0.0;
        __threadfence();
        atomicExch(&g_ticket, 0u);
    }
}

extern "C" void kernel_launch(void* const* d_in, const int* in_sizes, int n_in,
                              void* d_out, int out_size)
{
    const float* preds   = (const float*)d_in[0];
    const float* targets = (const float*)d_in[1];
    float* out = (float*)d_out;

    int n      = in_sizes[0];
    int rows   = n / CH;               // B*T = 131072
    int groups = rows / GROUP_ROWS;    // 4096

    cudaFuncSetAttribute(reg_loss_kernel,
                         cudaFuncAttributeMaxDynamicSharedMemorySize, SMEM_BYTES);

    // 296 blocks x 1024 thr; 193KB smem -> 1 resident block/SM, 2 waves
    reg_loss_kernel<<<296, THREADS, SMEM_BYTES>>>(preds, targets, out,
                                                  groups, rows);
}